// round 8
// baseline (speedup 1.0000x reference)
#include <cuda_runtime.h>
#include <cstdint>

// ---------------------------------------------------------------------------
// BinaryConnectNet forward:
//  conv1: dw3x3(g=3)+pw1x1(3->128), sign, maxpool2   -> a1 [1024][256pix][128c] int8
//  conv2: dw3x3(g=128)+pw1x1(128->256), sign, pool2  -> a2 [1024][16384] int8
//  fc1:   a2 @ W1^T + b1, sign                        -> a3 [1024][1024] int8
//  fc2:   a3 @ W2^T + b2                              -> out [1024][10] fp32
// ---------------------------------------------------------------------------

__device__ int8_t g_a1[1024 * 256 * 128];   // [n][pix(16x16)][c]
__device__ int8_t g_a2[1024 * 16384];       // [n][k] k = oc*64 + py*8 + px
__device__ int8_t g_a3[1024 * 1024];        // [n][j]

__device__ __forceinline__ float fsign(float v) {
    return (v > 0.f) ? 1.f : ((v < 0.f) ? -1.f : 0.f);
}
__device__ __forceinline__ int isign(int v) { return (v > 0) - (v < 0); }

// ---------------------------------------------------------------------------
// Kernel 1: conv1 dw + pw + sign + maxpool, one image per block, 256 threads.
// ---------------------------------------------------------------------------
__global__ __launch_bounds__(256) void k_conv1(
    const float* __restrict__ x,
    const float* __restrict__ w1dw, const float* __restrict__ b1dw,
    const float* __restrict__ w1pw, const float* __restrict__ b1pw)
{
    __shared__ float sx[3][32][32];
    __shared__ float sdw[3][32][32];
    __shared__ float swdw[27];
    __shared__ float sbdw[3];
    __shared__ float swpw[128 * 3];
    __shared__ float sbpw[128];

    const int n = blockIdx.x, tid = threadIdx.x;

    for (int i = tid; i < 3072; i += 256) ((float*)sx)[i] = x[n * 3072 + i];
    if (tid < 27)  swdw[tid] = fsign(w1dw[tid]);
    if (tid < 3)   sbdw[tid] = fsign(b1dw[tid]);
    for (int i = tid; i < 384; i += 256) swpw[i] = fsign(w1pw[i]);
    if (tid < 128) sbpw[tid] = fsign(b1pw[tid]);
    __syncthreads();

    // depthwise 3x3, pad=1 (fp32, natural tap order then +bias)
    for (int i = tid; i < 3072; i += 256) {
        int c = i >> 10, p = i & 1023, y = p >> 5, xx = p & 31;
        float acc = 0.f;
#pragma unroll
        for (int ky = 0; ky < 3; ky++) {
#pragma unroll
            for (int kx = 0; kx < 3; kx++) {
                int yy = y + ky - 1, xw = xx + kx - 1;
                if (yy >= 0 && yy < 32 && xw >= 0 && xw < 32)
                    acc += swdw[c * 9 + ky * 3 + kx] * sx[c][yy][xw];
            }
        }
        acc += sbdw[c];
        ((float*)sdw)[i] = acc;
    }
    __syncthreads();

    // pointwise 3->128, then sign+pool (sign monotone => pool pre-activation)
    for (int i = tid; i < 32768; i += 256) {
        int oc = i & 127, pp = i >> 7;           // pp: pooled pixel 0..255
        int oy = pp >> 4, ox = pp & 15;
        float w0 = swpw[oc * 3 + 0], w1 = swpw[oc * 3 + 1],
              w2 = swpw[oc * 3 + 2], bb = sbpw[oc];
        float vmax = -1e30f;
#pragma unroll
        for (int d = 0; d < 4; d++) {
            int y = 2 * oy + (d >> 1), xw = 2 * ox + (d & 1);
            float v = w0 * sdw[0][y][xw] + w1 * sdw[1][y][xw]
                    + w2 * sdw[2][y][xw] + bb;
            vmax = fmaxf(vmax, v);
        }
        g_a1[n * 32768 + pp * 128 + oc] = (int8_t)(int)fsign(vmax);
    }
}

// ---------------------------------------------------------------------------
// Kernel 2: conv2 dw (int) + pw (dp4a) + sign + maxpool, one image per block.
// Dynamic smem layout (99840 B):
//   [0      , 32768) s_a1 [pix][c] int8   (reused as s_a2 [oc][q] after dw)
//   [32768  , 65536) s_t  [pix][c] int8   (dw output, |t| <= 10)
//   [65536  , 98304) s_w  [oc][c]  int8   (pw weight signs)
//   [98304  , 99456) s_wd [c*9]    int8
//   [99456  , 99584) s_bd [c]      int8
//   [99584  , 99840) s_bp [oc]     int8
// ---------------------------------------------------------------------------
__global__ __launch_bounds__(256) void k_conv2(
    const float* __restrict__ w2dw, const float* __restrict__ b2dw,
    const float* __restrict__ w2pw, const float* __restrict__ b2pw)
{
    extern __shared__ char sm[];
    int8_t* s_a1 = (int8_t*)sm;
    int8_t* s_t  = (int8_t*)(sm + 32768);
    int8_t* s_w  = (int8_t*)(sm + 65536);
    int8_t* s_wd = (int8_t*)(sm + 98304);
    int8_t* s_bd = (int8_t*)(sm + 99456);
    int8_t* s_bp = (int8_t*)(sm + 99584);

    const int n = blockIdx.x, tid = threadIdx.x;

    {   // load a1 (coalesced uint4)
        const uint4* src = (const uint4*)(g_a1 + n * 32768);
        uint4* dst = (uint4*)s_a1;
        for (int i = tid; i < 2048; i += 256) dst[i] = src[i];
    }
    for (int i = tid; i < 1152; i += 256) s_wd[i] = (int8_t)(int)fsign(w2dw[i]);
    for (int i = tid; i < 32768; i += 256) s_w[i] = (int8_t)(int)fsign(w2pw[i]);
    if (tid < 128) s_bd[tid] = (int8_t)(int)fsign(b2dw[tid]);
    s_bp[tid] = (int8_t)(int)fsign(b2pw[tid]);
    __syncthreads();

    // depthwise 3x3 pad=1, exact int arithmetic
    for (int i = tid; i < 32768; i += 256) {
        int c = i & 127, p = i >> 7, y = p >> 4, xx = p & 15;
        int acc = (int)s_bd[c];
#pragma unroll
        for (int ky = 0; ky < 3; ky++) {
#pragma unroll
            for (int kx = 0; kx < 3; kx++) {
                int yy = y + ky - 1, xw = xx + kx - 1;
                if (yy >= 0 && yy < 16 && xw >= 0 && xw < 16)
                    acc += (int)s_wd[c * 9 + ky * 3 + kx]
                         * (int)s_a1[(yy * 16 + xw) * 128 + c];
            }
        }
        s_t[p * 128 + c] = (int8_t)acc;
    }
    __syncthreads();

    // pointwise 128->256 via dp4a; thread == output channel; fused sign+pool
    {
        const int oc = tid;
        uint32_t wreg[32];
        const uint32_t* wsrc = (const uint32_t*)s_w + oc * 32;
#pragma unroll
        for (int j = 0; j < 32; j++) wreg[j] = wsrc[j];
        const int bb = (int)s_bp[oc];
        int8_t* s_a2 = s_a1;                        // reuse region
        const uint4* t4 = (const uint4*)s_t;

        for (int q = 0; q < 64; q++) {
            int py = q >> 3, px = q & 7;
            int vmax = -2000000000;
#pragma unroll
            for (int d = 0; d < 4; d++) {
                int p = (2 * py + (d >> 1)) * 16 + 2 * px + (d & 1);
                int acc = bb;
#pragma unroll
                for (int jj = 0; jj < 8; jj++) {
                    uint4 t = t4[p * 8 + jj];       // broadcast across warp
                    acc = __dp4a((int)t.x, (int)wreg[jj * 4 + 0], acc);
                    acc = __dp4a((int)t.y, (int)wreg[jj * 4 + 1], acc);
                    acc = __dp4a((int)t.z, (int)wreg[jj * 4 + 2], acc);
                    acc = __dp4a((int)t.w, (int)wreg[jj * 4 + 3], acc);
                }
                vmax = max(vmax, acc);
            }
            s_a2[oc * 64 + q] = (int8_t)isign(vmax);
        }
    }
    __syncthreads();

    {   // coalesced write-out of a2 (16 KB)
        uint4* g = (uint4*)(g_a2 + n * 16384);
        const uint4* s2 = (const uint4*)s_a1;
        for (int i = tid; i < 1024; i += 256) g[i] = s2[i];
    }
}

// ---------------------------------------------------------------------------
// Kernel 3: fc1 GEMM  C[1024m][1024j] = a2[m][16k] @ W1[j][16k]^T, then sign.
// 64x64 tile / block, 256 threads, 4x4 per thread, BK=32, reg double buffer.
// ---------------------------------------------------------------------------
__global__ __launch_bounds__(256) void k_fc1(
    const float* __restrict__ Wf, const float* __restrict__ bf)
{
    __shared__ __align__(16) float As[2][32 * 68];
    __shared__ __align__(16) float Bs[2][32 * 68];

    const int tid = threadIdx.x;
    const int j0 = blockIdx.x * 64, m0 = blockIdx.y * 64;
    const int tm = tid >> 4, tn = tid & 15;
    const int lk = tid & 31, ljb = tid >> 5;   // loader: col lk, rows ljb+8*it

    float acc[4][4] = {};
    float  b_r[8];
    int8_t a_r[8];

    const float*  Bbase = Wf   + (size_t)(j0 + ljb) * 16384 + lk;
    const int8_t* Abase = g_a2 + (size_t)(m0 + ljb) * 16384 + lk;

#pragma unroll
    for (int it = 0; it < 8; it++) {
        b_r[it] = Bbase[(size_t)it * 8 * 16384];
        a_r[it] = Abase[(size_t)it * 8 * 16384];
    }
#pragma unroll
    for (int it = 0; it < 8; it++) {
        As[0][lk * 68 + ljb + 8 * it] = (float)a_r[it];
        Bs[0][lk * 68 + ljb + 8 * it] = b_r[it];
    }
    __syncthreads();

    int buf = 0;
    for (int kt = 0; kt < 512; kt++) {
        if (kt < 511) {
            const float*  bp = Bbase + (kt + 1) * 32;
            const int8_t* ap = Abase + (kt + 1) * 32;
#pragma unroll
            for (int it = 0; it < 8; it++) {
                b_r[it] = bp[(size_t)it * 8 * 16384];
                a_r[it] = ap[(size_t)it * 8 * 16384];
            }
        }
        const float* A = As[buf];
        const float* Bb = Bs[buf];
#pragma unroll
        for (int kk = 0; kk < 32; kk++) {
            float4 a4 = *(const float4*)(A  + kk * 68 + tm * 4);
            float4 b4 = *(const float4*)(Bb + kk * 68 + tn * 4);
            acc[0][0] += a4.x * b4.x; acc[0][1] += a4.x * b4.y;
            acc[0][2] += a4.x * b4.z; acc[0][3] += a4.x * b4.w;
            acc[1][0] += a4.y * b4.x; acc[1][1] += a4.y * b4.y;
            acc[1][2] += a4.y * b4.z; acc[1][3] += a4.y * b4.w;
            acc[2][0] += a4.z * b4.x; acc[2][1] += a4.z * b4.y;
            acc[2][2] += a4.z * b4.z; acc[2][3] += a4.z * b4.w;
            acc[3][0] += a4.w * b4.x; acc[3][1] += a4.w * b4.y;
            acc[3][2] += a4.w * b4.z; acc[3][3] += a4.w * b4.w;
        }
        if (kt < 511) {
            buf ^= 1;
#pragma unroll
            for (int it = 0; it < 8; it++) {
                As[buf][lk * 68 + ljb + 8 * it] = (float)a_r[it];
                Bs[buf][lk * 68 + ljb + 8 * it] = b_r[it];
            }
            __syncthreads();
        }
    }

#pragma unroll
    for (int i = 0; i < 4; i++) {
        int m = m0 + tm * 4 + i;
#pragma unroll
        for (int jj = 0; jj < 4; jj++) {
            int j = j0 + tn * 4 + jj;
            float v = acc[i][jj] + bf[j];
            g_a3[m * 1024 + j] = (int8_t)(int)fsign(v);
        }
    }
}

// ---------------------------------------------------------------------------
// Kernel 4: fc2  out[1024][10] = a3 @ W2^T + b2
// ---------------------------------------------------------------------------
__global__ __launch_bounds__(128) void k_fc2(
    const float* __restrict__ W2, const float* __restrict__ b2,
    float* __restrict__ out)
{
    const int n = blockIdx.x, tid = threadIdx.x;
    float acc[10] = {};
    const int8_t* a = g_a3 + n * 1024;
    for (int k = tid; k < 1024; k += 128) {
        float s = (float)a[k];
#pragma unroll
        for (int j = 0; j < 10; j++) acc[j] += s * W2[j * 1024 + k];
    }
#pragma unroll
    for (int j = 0; j < 10; j++)
#pragma unroll
        for (int off = 16; off; off >>= 1)
            acc[j] += __shfl_down_sync(0xffffffffu, acc[j], off);

    __shared__ float red[4][10];
    int w = tid >> 5, l = tid & 31;
    if (l == 0)
#pragma unroll
        for (int j = 0; j < 10; j++) red[w][j] = acc[j];
    __syncthreads();
    if (tid < 10) {
        float v = red[0][tid] + red[1][tid] + red[2][tid] + red[3][tid] + b2[tid];
        out[n * 10 + tid] = v;
    }
}

// ---------------------------------------------------------------------------
extern "C" void kernel_launch(void* const* d_in, const int* in_sizes, int n_in,
                              void* d_out, int out_size)
{
    const float* x    = (const float*)d_in[0];
    const float* w1dw = (const float*)d_in[1];
    const float* b1dw = (const float*)d_in[2];
    const float* w1pw = (const float*)d_in[3];
    const float* b1pw = (const float*)d_in[4];
    const float* w2dw = (const float*)d_in[5];
    const float* b2dw = (const float*)d_in[6];
    const float* w2pw = (const float*)d_in[7];
    const float* b2pw = (const float*)d_in[8];
    const float* fc1w = (const float*)d_in[9];
    const float* fc1b = (const float*)d_in[10];
    const float* fc2w = (const float*)d_in[11];
    const float* fc2b = (const float*)d_in[12];
    float* out = (float*)d_out;

    const int SMEM2 = 99840;
    cudaFuncSetAttribute(k_conv2, cudaFuncAttributeMaxDynamicSharedMemorySize, SMEM2);

    k_conv1<<<1024, 256>>>(x, w1dw, b1dw, w1pw, b1pw);
    k_conv2<<<1024, 256, SMEM2>>>(w2dw, b2dw, w2pw, b2pw);
    k_fc1<<<dim3(16, 16), 256>>>(fc1w, fc1b);
    k_fc2<<<1024, 128>>>(fc2w, fc2b, out);
}